// round 16
// baseline (speedup 1.0000x reference)
#include <cuda_runtime.h>
#include <stdint.h>

#define K 8
#define C 256
#define INF_F __int_as_float(0x7F800000)
#define FULL 0xFFFFFFFFu

// ---------------------------------------------------------------------------
// Scratch. Point regions: stage2 [0,8192), stage1 [8192,10240), stage0 [10240,10752).
// 16-pt group regions: stage2 [0,512), stage1 [512,640), stage0 [640,672).
// ---------------------------------------------------------------------------
static __device__ float4 g_cx[10752];
static __device__ float4 g_cn[10752];
static __device__ unsigned long long g_code[10752];   // sorted morton | local idx
static __device__ float4 g_sx[10752];
static __device__ float4 g_sn[10752];
static __device__ int    g_sid[10752];
static __device__ float4 g_gc[672];                   // 16-pt group center + radius
static __device__ float  g_wiv[2 * 16384 * 16 + 2 * 4096 * 16 + 2 * 1024 * 16];
static __device__ float  g_x1[2 * 1024 * 256];
static __device__ float  g_x2[2 * 4096 * 256];

#define WOFF2 0
#define WOFF1 (2 * 16384 * 16)
#define WOFF0 (2 * 16384 * 16 + 2 * 4096 * 16)

// ---------------------------------------------------------------------------
__device__ __forceinline__ unsigned expand_bits(unsigned v) {
    v &= 0x3FFu;
    v = (v | (v << 16)) & 0x030000FFu;
    v = (v | (v << 8))  & 0x0300F00Fu;
    v = (v | (v << 4))  & 0x030C30C3u;
    v = (v | (v << 2))  & 0x09249249u;
    return v;
}
__device__ __forceinline__ unsigned quant10(float x) {
    float u = (x + 4.2f) * (1024.0f / 8.4f);
    u = fminf(fmaxf(u, 0.0f), 1023.0f);
    return (unsigned)u;
}

// ---------------------------------------------------------------------------
// Fused pack + counting sort + reorder + 16-pt bounding spheres.
// ---------------------------------------------------------------------------
__global__ void __launch_bounds__(1024) csort_kernel(
    const float* __restrict__ x1p, const float* __restrict__ n1p,
    const float* __restrict__ x2p, const float* __restrict__ n2p,
    const float* __restrict__ x3p, const float* __restrict__ n3p)
{
    static const int tb[6]   = {0, 4096, 8192, 9216, 10240, 10496};
    static const int ts[6]   = {4096, 4096, 1024, 1024, 256, 256};
    static const int tbin[6] = {2048, 2048, 512, 512, 128, 128};
    static const int tsh[6]  = {19, 19, 21, 21, 23, 23};
    static const int tgb[6]  = {0, 256, 512, 576, 640, 656};   // 16-pt group bases

    __shared__ unsigned long long skeys[4096];
    __shared__ int hist[2048];

    const int seg = blockIdx.x;
    const int base = tb[seg], S = ts[seg], bins = tbin[seg], shift = tsh[seg];
    const int tid = threadIdx.x;

    const float* xs;
    const float* ns;
    if (seg < 2)      { xs = x1p; ns = n1p; }
    else if (seg < 4) { xs = x2p; ns = n2p; }
    else              { xs = x3p; ns = n3p; }
    const int boff = (seg & 1) * S;

    for (int i = tid; i < S; i += 1024) {
        int j = boff + i;
        float x = xs[3 * j], y = xs[3 * j + 1], z = xs[3 * j + 2];
        g_cx[base + i] = make_float4(x, y, z, 0.5f * (x * x + y * y + z * z));
        float a = ns[3 * j], b = ns[3 * j + 1], c = ns[3 * j + 2];
        g_cn[base + i] = make_float4(a, b, c, 0.5f * (a * a + b * b + c * c));
        unsigned code = (expand_bits(quant10(x)) << 2) |
                        (expand_bits(quant10(y)) << 1) |
                         expand_bits(quant10(z));
        skeys[i] = ((unsigned long long)code << 32) | (unsigned)i;
    }
    for (int i = tid; i < bins; i += 1024) hist[i] = 0;
    __syncthreads();
    for (int i = tid; i < S; i += 1024)
        atomicAdd(&hist[(unsigned)(skeys[i] >> 32) >> shift], 1);
    __syncthreads();
    for (int dstep = 1; dstep < bins; dstep <<= 1) {
        for (int i = tid; i < bins / (2 * dstep); i += 1024) {
            int idx = (i + 1) * 2 * dstep - 1;
            hist[idx] += hist[idx - dstep];
        }
        __syncthreads();
    }
    if (tid == 0) hist[bins - 1] = 0;
    __syncthreads();
    for (int dstep = bins >> 1; dstep >= 1; dstep >>= 1) {
        for (int i = tid; i < bins / (2 * dstep); i += 1024) {
            int idx = (i + 1) * 2 * dstep - 1;
            int t = hist[idx - dstep];
            hist[idx - dstep] = hist[idx];
            hist[idx] += t;
        }
        __syncthreads();
    }
    for (int i = tid; i < S; i += 1024) {
        unsigned long long key = skeys[i];
        int bin = (unsigned)(key >> 32) >> shift;
        int pos = atomicAdd(&hist[bin], 1);
        g_code[base + pos] = key;
    }
    __syncthreads();

    int warp = tid >> 5, lane = tid & 31;
    int nBlk = S / 32;
    for (int g = warp; g < nBlk; g += 32) {
        unsigned long long key = g_code[base + g * 32 + lane];
        int li = (int)(unsigned)key;
        float4 v = g_cx[base + li];
        int dst = base + g * 32 + lane;
        g_sx[dst] = v;
        g_sn[dst] = g_cn[base + li];
        g_sid[dst] = li;

        float mnx = v.x, mxx = v.x, mny = v.y, mxy = v.y, mnz = v.z, mxz = v.z;
#pragma unroll
        for (int off = 8; off; off >>= 1) {   // within 16-lane halves
            mnx = fminf(mnx, __shfl_xor_sync(FULL, mnx, off));
            mxx = fmaxf(mxx, __shfl_xor_sync(FULL, mxx, off));
            mny = fminf(mny, __shfl_xor_sync(FULL, mny, off));
            mxy = fmaxf(mxy, __shfl_xor_sync(FULL, mxy, off));
            mnz = fminf(mnz, __shfl_xor_sync(FULL, mnz, off));
            mxz = fmaxf(mxz, __shfl_xor_sync(FULL, mxz, off));
        }
        float cxc = (mnx + mxx) * 0.5f, cyc = (mny + mxy) * 0.5f, czc = (mnz + mxz) * 0.5f;
        float dx = v.x - cxc, dy = v.y - cyc, dz = v.z - czc;
        float d2 = fmaf(dx, dx, fmaf(dy, dy, dz * dz));
#pragma unroll
        for (int off = 8; off; off >>= 1)
            d2 = fmaxf(d2, __shfl_xor_sync(FULL, d2, off));
        if ((lane & 15) == 0)
            g_gc[tgb[seg] + g * 2 + (lane >> 4)] =
                make_float4(cxc, cyc, czc, sqrtf(d2));
    }
}

// ---------------------------------------------------------------------------
// Distributed warp-resident sorted top-8: lane l<8 holds l-th smallest.
// ---------------------------------------------------------------------------
__device__ __forceinline__ void warp_insert(float cd, int ci,
                                            float& d_top, int& i_top, int lane)
{
    unsigned pm = __ballot_sync(FULL, cd < d_top) & 0xFFu;
    float dp = __shfl_up_sync(FULL, d_top, 1);
    int ip = __shfl_up_sync(FULL, i_top, 1);
    if (pm) {
        int p = __ffs(pm) - 1;
        if (lane >= p && lane < 8) {
            d_top = (lane == p) ? cd : dp;
            i_top = (lane == p) ? ci : ip;
        }
    }
}

// ---------------------------------------------------------------------------
// topk per-query: warp per query, 16-pt sphere pruning, paired-group eval.
// ---------------------------------------------------------------------------
template <int S, int G>
__device__ __forceinline__ void topk_query(
    const float* __restrict__ xyzF, const float* __restrict__ nrmF,
    int N, int base, int gbase, int wbase, int b, int n, int lane)
{
    const float4* __restrict__ sx = g_sx + base + b * S;
    const float4* __restrict__ sn = g_sn + base + b * S;
    const float4* __restrict__ gc = g_gc + gbase + b * G;

    const float* p = xyzF + ((size_t)b * N + n) * 3;
    const float qx = p[0], qy = p[1], qz = p[2];
    const float qh = 0.5f * (qx * qx + qy * qy + qz * qz);
    const float* q = nrmF + ((size_t)b * N + n) * 3;
    const float ux = q[0], uy = q[1], uz = q[2];
    const float uh = 0.5f * (ux * ux + uy * uy + uz * uz);

    constexpr int GS = (G + 31) / 32;
    const int hlane = lane & 15;
    const int half = lane >> 4;

    // ---- Phase 1: nearest 16-pt group ----
    float bd2 = INF_F;
    unsigned bcode = 0;
#pragma unroll
    for (int s = 0; s < GS; s++) {
        int gi = s * 32 + lane;
        float4 cc = make_float4(0.0f, 0.0f, 0.0f, 0.0f);
        if (G >= 32 || gi < G) cc = __ldg(gc + gi);
        float dx = qx - cc.x, dy = qy - cc.y, dz = qz - cc.z;
        float d2 = fmaf(dx, dx, fmaf(dy, dy, dz * dz));
        if (!(G >= 32 || gi < G)) d2 = INF_F;
        if (d2 < bd2) { bd2 = d2; bcode = (unsigned)(s << 5) | (unsigned)lane; }
    }
    unsigned kmin = (__float_as_uint(bd2) & 0xFFFFFF00u) | bcode;
    kmin = __reduce_min_sync(FULL, kmin);
    const int gp = (int)(kmin & 0xFFu);
    const int gq = gp ^ 1;

    float d_top = INF_F;
    int   i_top = 0;

    // ---- Warm-up: eval pair (gp, gq) ----
    {
        int pos = (half ? gq : gp) * 16 + hlane;
        float4 c = __ldg(sx + pos);
        float sd = fmaf(-qz, c.z, fmaf(-qy, c.y, fmaf(-qx, c.x, c.w)));
        float dxy = sqrtf(fmaxf(2.0f * (sd + qh), 0.0f));
        float4 nc = __ldg(sn + pos);
        float nd = fmaf(-uz, nc.z, fmaf(-uy, nc.y, fmaf(-ux, nc.x, nc.w)));
        float dn = sqrtf(fmaxf(2.0f * (nd + uh), 0.0f));
        float tot = dxy + 1.0f / (1.0f + __expf(-dn));

        float qm = fminf(tot, __shfl_xor_sync(FULL, tot, 1));
        qm = fminf(qm, __shfl_xor_sync(FULL, qm, 2));
        float ub = fmaxf(qm, __shfl_xor_sync(FULL, qm, 4));
        ub = fmaxf(ub, __shfl_xor_sync(FULL, ub, 8));
        ub = fmaxf(ub, __shfl_xor_sync(FULL, ub, 16));

        unsigned m2 = __ballot_sync(FULL, tot <= ub);
        while (m2) {
            int sp = __ffs(m2) - 1;
            m2 &= m2 - 1;
            float cd = __shfl_sync(FULL, tot, sp);
            int ci = __shfl_sync(FULL, pos, sp);
            warp_insert(cd, ci, d_top, i_top, lane);
        }
    }
    float kth = __shfl_sync(FULL, d_top, 7);
    float kth05 = kth - 0.5f;

    // ---- Phase 2: sphere-pruned sweep, two 16-pt groups per iteration ----
#pragma unroll
    for (int s = 0; s < GS; s++) {
        int gi = s * 32 + lane;
        float sgv = INF_F;
        if (G >= 32 || gi < G) {
            float4 cc = __ldg(gc + gi);
            float dx = qx - cc.x, dy = qy - cc.y, dz = qz - cc.z;
            sgv = sqrtf(fmaf(dx, dx, fmaf(dy, dy, dz * dz))) - cc.w;
        }
        bool surv = (sgv < kth05) && (gi != gp) && (gi != gq);
        unsigned m = __ballot_sync(FULL, surv);
        while (m) {
            int s1 = __ffs(m) - 1;
            m &= m - 1;
            int s2 = -1;
            if (m) { s2 = __ffs(m) - 1; m &= m - 1; }
            int ga = s * 32 + s1;
            int gb = (s2 >= 0) ? s * 32 + s2 : ga;
            bool act = (half == 0) || (s2 >= 0);
            int pos = (half ? gb : ga) * 16 + hlane;
            float4 c = __ldg(sx + pos);
            float sd = fmaf(-qz, c.z, fmaf(-qy, c.y, fmaf(-qx, c.x, c.w)));
            float dxy = sqrtf(fmaxf(2.0f * (sd + qh), 0.0f));
            float tot = INF_F;
            if (act && dxy < kth05) {
                float4 nc = __ldg(sn + pos);
                float nd = fmaf(-uz, nc.z,
                                fmaf(-uy, nc.y, fmaf(-ux, nc.x, nc.w)));
                float dn = sqrtf(fmaxf(2.0f * (nd + uh), 0.0f));
                tot = dxy + 1.0f / (1.0f + __expf(-dn));
            }
            unsigned m2 = __ballot_sync(FULL, tot < kth);
            if (m2) {
                while (m2) {
                    int sp = __ffs(m2) - 1;
                    m2 &= m2 - 1;
                    float cd = __shfl_sync(FULL, tot, sp);
                    int ci = __shfl_sync(FULL, pos, sp);
                    warp_insert(cd, ci, d_top, i_top, lane);
                }
                kth = __shfl_sync(FULL, d_top, 7);
                kth05 = kth - 0.5f;
            }
        }
    }

    // ---- Output: 8 lanes in parallel ----
    float r = (lane < 8) ? 1.0f / (d_top + 1e-8f) : 0.0f;
    float sum = r;
#pragma unroll
    for (int off = 1; off < 32; off <<= 1)
        sum += __shfl_xor_sync(FULL, sum, off);
    if (lane < 8) {
        float w = r / sum;
        int oi = __ldg(g_sid + base + b * S + i_top);
        float* o = g_wiv + wbase + ((size_t)b * N + n) * 16;
        o[lane] = w;
        o[8 + lane] = __int_as_float(oi);
    }
}

// ---------------------------------------------------------------------------
// Shared interp body: one (query, 64-lane slice) unit.
// ---------------------------------------------------------------------------
__device__ __forceinline__ void interp_one(
    const float* __restrict__ p1, const float* __restrict__ p2,
    float* __restrict__ out, int N, int S, int wbase, int b, int n, int l)
{
    const float4* wv = (const float4*)(g_wiv + wbase + ((size_t)b * N + n) * 16);
    float4 w0 = __ldg(wv + 0), w1 = __ldg(wv + 1);
    float4 f0 = __ldg(wv + 2), f1 = __ldg(wv + 3);

    const float4* __restrict__ P = (const float4*)p2 + (size_t)b * S * (C / 4);
    float4 acc;
    {
        float4 r0 = __ldg(P + (size_t)__float_as_int(f0.x) * (C / 4) + l);
        acc.x = w0.x * r0.x; acc.y = w0.x * r0.y;
        acc.z = w0.x * r0.z; acc.w = w0.x * r0.w;
    }
#define GATHER(W, IDX)                                                         \
    {                                                                          \
        float4 r_ = __ldg(P + (size_t)__float_as_int(IDX) * (C / 4) + l);      \
        acc.x = fmaf(W, r_.x, acc.x); acc.y = fmaf(W, r_.y, acc.y);            \
        acc.z = fmaf(W, r_.z, acc.z); acc.w = fmaf(W, r_.w, acc.w);            \
    }
    GATHER(w0.y, f0.y) GATHER(w0.z, f0.z) GATHER(w0.w, f0.w)
    GATHER(w1.x, f1.x) GATHER(w1.y, f1.y) GATHER(w1.z, f1.z) GATHER(w1.w, f1.w)
#undef GATHER

    const size_t qo = ((size_t)b * N + n) * (C / 4) + l;
    float4 pv = __ldg((const float4*)p1 + qo);
    float4 o;
    o.x = (fmaxf(pv.x, acc.x) + (pv.x + acc.x) * 0.5f) * 0.5f;
    o.y = (fmaxf(pv.y, acc.y) + (pv.y + acc.y) * 0.5f) * 0.5f;
    o.z = (fmaxf(pv.z, acc.z) + (pv.z + acc.z) * 0.5f) * 0.5f;
    o.w = (fmaxf(pv.w, acc.w) + (pv.w + acc.w) * 0.5f) * 0.5f;
    ((float4*)out)[qo] = o;
}

// ---------------------------------------------------------------------------
// topk stage-2 only (the large one): blocks [0,4096).
// ---------------------------------------------------------------------------
__global__ void __launch_bounds__(256, 7) topk2_kernel(
    const float* __restrict__ x0, const float* __restrict__ n0)
{
    int b = blockIdx.x >> 11, n = (blockIdx.x & 2047) * 8 + (threadIdx.x >> 5);
    topk_query<4096, 256>(x0, n0, 16384, 0, 0, WOFF2, b, n, threadIdx.x & 31);
}

// ---------------------------------------------------------------------------
// topk stages 0+1 (+fused stage0 interp): blocks [0,1024) stage1, [1024,1280) stage0.
// ---------------------------------------------------------------------------
__global__ void __launch_bounds__(256, 7) topk01_kernel(
    const float* __restrict__ x1, const float* __restrict__ n1,
    const float* __restrict__ x2, const float* __restrict__ n2,
    const float* __restrict__ feat2, const float* __restrict__ feat3,
    float* __restrict__ x1out)
{
    const int bid = blockIdx.x;
    const int warp = threadIdx.x >> 5;
    const int lane = threadIdx.x & 31;
    if (bid < 1024) {
        int b = bid >> 9, n = (bid & 511) * 8 + warp;
        topk_query<1024, 64>(x1, n1, 4096, 8192, 512, WOFF1, b, n, lane);
    } else {
        int lb = bid - 1024, b = lb >> 7, n = (lb & 127) * 8 + warp;
        topk_query<256, 16>(x2, n2, 1024, 10240, 640, WOFF0, b, n, lane);
        __syncthreads();
        int n_base = (lb & 127) * 8;
#pragma unroll
        for (int rep = 0; rep < 2; rep++) {
            int slot = threadIdx.x + rep * 256;
            interp_one(feat2, feat3, x1out, 1024, 256, WOFF0,
                       b, n_base + (slot >> 6), slot & 63);
        }
    }
}

// ---------------------------------------------------------------------------
// Interpolate: 64 lanes (float4 channels) per query, 4 queries per block.
// ---------------------------------------------------------------------------
__global__ void __launch_bounds__(256) interp_kernel(
    const float* __restrict__ p1, const float* __restrict__ p2,
    float* __restrict__ out, int N, int S, int wbase)
{
    const int b = blockIdx.y;
    const int g = threadIdx.x >> 6;
    const int l = threadIdx.x & 63;
    const int n = blockIdx.x * 4 + g;
    interp_one(p1, p2, out, N, S, wbase, b, n, l);
}

// ---------------------------------------------------------------------------
extern "C" void kernel_launch(void* const* d_in, const int* in_sizes, int n_in,
                              void* d_out, int out_size)
{
    const int B = 2;
    const int Ns[4] = {16384, 4096, 1024, 256};
    const float* xyz[4] = {0, 0, 0, 0};
    const float* nrm[4] = {0, 0, 0, 0};
    const float* feat[4] = {0, 0, 0, 0};

    for (int i = 0; i < n_in; i++) {
        long long cnt = in_sizes[i];
        for (int r = 0; r < 4; r++) {
            long long small = (long long)B * Ns[r] * 3;
            long long big = (long long)B * Ns[r] * C;
            if (cnt == small) {
                if (!xyz[r]) xyz[r] = (const float*)d_in[i];
                else if (!nrm[r]) nrm[r] = (const float*)d_in[i];
                break;
            } else if (cnt == big) {
                if (!feat[r]) feat[r] = (const float*)d_in[i];
                break;
            }
        }
    }

    float* out = (float*)d_out;
    float *x1, *x2;
    cudaGetSymbolAddress((void**)&x1, g_x1);
    cudaGetSymbolAddress((void**)&x2, g_x2);

    // One-time side stream + events (host-side objects, no device memory).
    static cudaStream_t s1 = nullptr;
    static cudaEvent_t ev0 = nullptr, ev1 = nullptr;
    if (!s1) {
        cudaStreamCreateWithFlags(&s1, cudaStreamNonBlocking);
        cudaEventCreateWithFlags(&ev0, cudaEventDisableTiming);
        cudaEventCreateWithFlags(&ev1, cudaEventDisableTiming);
    }

    // ---- s0: preprocess ----
    csort_kernel<<<6, 1024>>>(xyz[1], nrm[1], xyz[2], nrm[2], xyz[3], nrm[3]);
    cudaEventRecord(ev0, 0);

    // ---- fork: s1 runs small topk stages + interp chain up to x2 ----
    cudaStreamWaitEvent(s1, ev0, 0);
    topk01_kernel<<<1280, 256, 0, s1>>>(xyz[1], nrm[1], xyz[2], nrm[2],
                                        feat[2], feat[3], x1);
    interp_kernel<<<dim3(4096 / 4, B), 256, 0, s1>>>(feat[1], x1, x2,
                                                     4096, 1024, WOFF1);
    cudaEventRecord(ev1, s1);

    // ---- s0: the big stage-2 topk runs concurrently with s1 ----
    topk2_kernel<<<4096, 256>>>(xyz[0], nrm[0]);

    // ---- join: final interp needs x2 (s1) and stage-2 topk (s0) ----
    cudaStreamWaitEvent(0, ev1, 0);
    interp_kernel<<<dim3(16384 / 4, B), 256>>>(feat[0], x2, out,
                                               16384, 4096, WOFF2);
}

// round 17
// speedup vs baseline: 1.0722x; 1.0722x over previous
#include <cuda_runtime.h>
#include <stdint.h>

#define K 8
#define C 256
#define INF_F __int_as_float(0x7F800000)
#define FULL 0xFFFFFFFFu

// ---------------------------------------------------------------------------
// Scratch. Point regions: stage2 [0,8192), stage1 [8192,10240), stage0 [10240,10752).
// 16-pt group regions: stage2 [0,512), stage1 [512,640), stage0 [640,672).
// ---------------------------------------------------------------------------
static __device__ float4 g_cx[10752];
static __device__ float4 g_cn[10752];
static __device__ unsigned long long g_code[10752];   // sorted morton | local idx
static __device__ float4 g_sx[10752];
static __device__ float4 g_sn[10752];
static __device__ int    g_sid[10752];
static __device__ float4 g_gc[672];                   // 16-pt group center + radius
static __device__ float  g_wiv[2 * 16384 * 16 + 2 * 4096 * 16 + 2 * 1024 * 16];
static __device__ float  g_x1[2 * 1024 * 256];
static __device__ float  g_x2[2 * 4096 * 256];

#define WOFF2 0
#define WOFF1 (2 * 16384 * 16)
#define WOFF0 (2 * 16384 * 16 + 2 * 4096 * 16)

// ---------------------------------------------------------------------------
__device__ __forceinline__ unsigned expand_bits(unsigned v) {
    v &= 0x3FFu;
    v = (v | (v << 16)) & 0x030000FFu;
    v = (v | (v << 8))  & 0x0300F00Fu;
    v = (v | (v << 4))  & 0x030C30C3u;
    v = (v | (v << 2))  & 0x09249249u;
    return v;
}
__device__ __forceinline__ unsigned quant10(float x) {
    float u = (x + 4.2f) * (1024.0f / 8.4f);
    u = fminf(fmaxf(u, 0.0f), 1023.0f);
    return (unsigned)u;
}

// ---------------------------------------------------------------------------
// Fused pack + counting sort + reorder + 16-pt bounding spheres.
// ---------------------------------------------------------------------------
__global__ void __launch_bounds__(1024) csort_kernel(
    const float* __restrict__ x1p, const float* __restrict__ n1p,
    const float* __restrict__ x2p, const float* __restrict__ n2p,
    const float* __restrict__ x3p, const float* __restrict__ n3p)
{
    static const int tb[6]   = {0, 4096, 8192, 9216, 10240, 10496};
    static const int ts[6]   = {4096, 4096, 1024, 1024, 256, 256};
    static const int tbin[6] = {2048, 2048, 512, 512, 128, 128};
    static const int tsh[6]  = {19, 19, 21, 21, 23, 23};
    static const int tgb[6]  = {0, 256, 512, 576, 640, 656};   // 16-pt group bases

    __shared__ unsigned long long skeys[4096];
    __shared__ int hist[2048];

    const int seg = blockIdx.x;
    const int base = tb[seg], S = ts[seg], bins = tbin[seg], shift = tsh[seg];
    const int tid = threadIdx.x;

    const float* xs;
    const float* ns;
    if (seg < 2)      { xs = x1p; ns = n1p; }
    else if (seg < 4) { xs = x2p; ns = n2p; }
    else              { xs = x3p; ns = n3p; }
    const int boff = (seg & 1) * S;

    for (int i = tid; i < S; i += 1024) {
        int j = boff + i;
        float x = xs[3 * j], y = xs[3 * j + 1], z = xs[3 * j + 2];
        g_cx[base + i] = make_float4(x, y, z, 0.5f * (x * x + y * y + z * z));
        float a = ns[3 * j], b = ns[3 * j + 1], c = ns[3 * j + 2];
        g_cn[base + i] = make_float4(a, b, c, 0.5f * (a * a + b * b + c * c));
        unsigned code = (expand_bits(quant10(x)) << 2) |
                        (expand_bits(quant10(y)) << 1) |
                         expand_bits(quant10(z));
        skeys[i] = ((unsigned long long)code << 32) | (unsigned)i;
    }
    for (int i = tid; i < bins; i += 1024) hist[i] = 0;
    __syncthreads();
    for (int i = tid; i < S; i += 1024)
        atomicAdd(&hist[(unsigned)(skeys[i] >> 32) >> shift], 1);
    __syncthreads();
    for (int dstep = 1; dstep < bins; dstep <<= 1) {
        for (int i = tid; i < bins / (2 * dstep); i += 1024) {
            int idx = (i + 1) * 2 * dstep - 1;
            hist[idx] += hist[idx - dstep];
        }
        __syncthreads();
    }
    if (tid == 0) hist[bins - 1] = 0;
    __syncthreads();
    for (int dstep = bins >> 1; dstep >= 1; dstep >>= 1) {
        for (int i = tid; i < bins / (2 * dstep); i += 1024) {
            int idx = (i + 1) * 2 * dstep - 1;
            int t = hist[idx - dstep];
            hist[idx - dstep] = hist[idx];
            hist[idx] += t;
        }
        __syncthreads();
    }
    for (int i = tid; i < S; i += 1024) {
        unsigned long long key = skeys[i];
        int bin = (unsigned)(key >> 32) >> shift;
        int pos = atomicAdd(&hist[bin], 1);
        g_code[base + pos] = key;
    }
    __syncthreads();

    int warp = tid >> 5, lane = tid & 31;
    int nBlk = S / 32;
    for (int g = warp; g < nBlk; g += 32) {
        unsigned long long key = g_code[base + g * 32 + lane];
        int li = (int)(unsigned)key;
        float4 v = g_cx[base + li];
        int dst = base + g * 32 + lane;
        g_sx[dst] = v;
        g_sn[dst] = g_cn[base + li];
        g_sid[dst] = li;

        float mnx = v.x, mxx = v.x, mny = v.y, mxy = v.y, mnz = v.z, mxz = v.z;
#pragma unroll
        for (int off = 8; off; off >>= 1) {   // within 16-lane halves
            mnx = fminf(mnx, __shfl_xor_sync(FULL, mnx, off));
            mxx = fmaxf(mxx, __shfl_xor_sync(FULL, mxx, off));
            mny = fminf(mny, __shfl_xor_sync(FULL, mny, off));
            mxy = fmaxf(mxy, __shfl_xor_sync(FULL, mxy, off));
            mnz = fminf(mnz, __shfl_xor_sync(FULL, mnz, off));
            mxz = fmaxf(mxz, __shfl_xor_sync(FULL, mxz, off));
        }
        float cxc = (mnx + mxx) * 0.5f, cyc = (mny + mxy) * 0.5f, czc = (mnz + mxz) * 0.5f;
        float dx = v.x - cxc, dy = v.y - cyc, dz = v.z - czc;
        float d2 = fmaf(dx, dx, fmaf(dy, dy, dz * dz));
#pragma unroll
        for (int off = 8; off; off >>= 1)
            d2 = fmaxf(d2, __shfl_xor_sync(FULL, d2, off));
        if ((lane & 15) == 0)
            g_gc[tgb[seg] + g * 2 + (lane >> 4)] =
                make_float4(cxc, cyc, czc, sqrtf(d2));
    }
}

// ---------------------------------------------------------------------------
// Distributed warp-resident sorted top-8: lane l<8 holds l-th smallest.
// ---------------------------------------------------------------------------
__device__ __forceinline__ void warp_insert(float cd, int ci,
                                            float& d_top, int& i_top, int lane)
{
    unsigned pm = __ballot_sync(FULL, cd < d_top) & 0xFFu;
    float dp = __shfl_up_sync(FULL, d_top, 1);
    int ip = __shfl_up_sync(FULL, i_top, 1);
    if (pm) {
        int p = __ffs(pm) - 1;
        if (lane >= p && lane < 8) {
            d_top = (lane == p) ? cd : dp;
            i_top = (lane == p) ? ci : ip;
        }
    }
}

// ---------------------------------------------------------------------------
// topk per-query: warp per query, 16-pt sphere pruning (squared compares),
// paired-group eval with pr-gated lazy sqrt+nrm path.
//   dxy < kth05  <=>  sd < pr,  pr = 0.5*kth05^2 - qh   (exact, kth05 > 0)
// ---------------------------------------------------------------------------
template <int S, int G>
__device__ __forceinline__ void topk_query(
    const float* __restrict__ xyzF, const float* __restrict__ nrmF,
    int N, int base, int gbase, int wbase, int b, int n, int lane)
{
    const float4* __restrict__ sx = g_sx + base + b * S;
    const float4* __restrict__ sn = g_sn + base + b * S;
    const float4* __restrict__ gc = g_gc + gbase + b * G;

    const float* p = xyzF + ((size_t)b * N + n) * 3;
    const float qx = p[0], qy = p[1], qz = p[2];
    const float qh = 0.5f * (qx * qx + qy * qy + qz * qz);
    const float* q = nrmF + ((size_t)b * N + n) * 3;
    const float ux = q[0], uy = q[1], uz = q[2];
    const float uh = 0.5f * (ux * ux + uy * uy + uz * uz);

    constexpr int GS = (G + 31) / 32;
    const int hlane = lane & 15;
    const int half = lane >> 4;

    // ---- Phase 1: nearest 16-pt group (d2 only, no sqrt) ----
    float bd2 = INF_F;
    unsigned bcode = 0;
#pragma unroll
    for (int s = 0; s < GS; s++) {
        int gi = s * 32 + lane;
        float4 cc = make_float4(0.0f, 0.0f, 0.0f, 0.0f);
        if (G >= 32 || gi < G) cc = __ldg(gc + gi);
        float dx = qx - cc.x, dy = qy - cc.y, dz = qz - cc.z;
        float d2 = fmaf(dx, dx, fmaf(dy, dy, dz * dz));
        if (!(G >= 32 || gi < G)) d2 = INF_F;
        if (d2 < bd2) { bd2 = d2; bcode = (unsigned)(s << 5) | (unsigned)lane; }
    }
    unsigned kmin = (__float_as_uint(bd2) & 0xFFFFFF00u) | bcode;
    kmin = __reduce_min_sync(FULL, kmin);
    const int gp = (int)(kmin & 0xFFu);
    const int gq = gp ^ 1;

    float d_top = INF_F;
    int   i_top = 0;

    // ---- Warm-up: eval pair (gp, gq) fully ----
    {
        int pos = (half ? gq : gp) * 16 + hlane;
        float4 c = __ldg(sx + pos);
        float sd = fmaf(-qz, c.z, fmaf(-qy, c.y, fmaf(-qx, c.x, c.w)));
        float dxy = sqrtf(fmaxf(2.0f * (sd + qh), 0.0f));
        float4 nc = __ldg(sn + pos);
        float nd = fmaf(-uz, nc.z, fmaf(-uy, nc.y, fmaf(-ux, nc.x, nc.w)));
        float dn = sqrtf(fmaxf(2.0f * (nd + uh), 0.0f));
        float tot = dxy + 1.0f / (1.0f + __expf(-dn));

        float qm = fminf(tot, __shfl_xor_sync(FULL, tot, 1));
        qm = fminf(qm, __shfl_xor_sync(FULL, qm, 2));
        float ub = fmaxf(qm, __shfl_xor_sync(FULL, qm, 4));
        ub = fmaxf(ub, __shfl_xor_sync(FULL, ub, 8));
        ub = fmaxf(ub, __shfl_xor_sync(FULL, ub, 16));

        unsigned m2 = __ballot_sync(FULL, tot <= ub);
        while (m2) {
            int sp = __ffs(m2) - 1;
            m2 &= m2 - 1;
            float cd = __shfl_sync(FULL, tot, sp);
            int ci = __shfl_sync(FULL, pos, sp);
            warp_insert(cd, ci, d_top, i_top, lane);
        }
    }
    float kth = __shfl_sync(FULL, d_top, 7);
    float kth05 = kth - 0.5f;
    float pr = fmaf(0.5f * kth05, kth05, -qh);

    // ---- Phase 2: sphere-pruned sweep (squared compare), pr-gated eval ----
#pragma unroll
    for (int s = 0; s < GS; s++) {
        int gi = s * 32 + lane;
        float d2 = INF_F, rad = 0.0f;
        if (G >= 32 || gi < G) {
            float4 cc = __ldg(gc + gi);
            float dx = qx - cc.x, dy = qy - cc.y, dz = qz - cc.z;
            d2 = fmaf(dx, dx, fmaf(dy, dy, dz * dz));
            rad = cc.w;
        }
        float t = kth05 + rad;
        bool surv = (d2 < t * t) && (gi != gp) && (gi != gq);
        unsigned m = __ballot_sync(FULL, surv);
        while (m) {
            int s1 = __ffs(m) - 1;
            m &= m - 1;
            int s2 = -1;
            if (m) { s2 = __ffs(m) - 1; m &= m - 1; }
            int ga = s * 32 + s1;
            int gb = (s2 >= 0) ? s * 32 + s2 : ga;
            bool act = (half == 0) || (s2 >= 0);
            int pos = (half ? gb : ga) * 16 + hlane;
            float4 c = __ldg(sx + pos);
            float sd = fmaf(-qz, c.z, fmaf(-qy, c.y, fmaf(-qx, c.x, c.w)));
            bool cand = act && (sd < pr);       // exact gate: dxy < kth05
            unsigned mm = __ballot_sync(FULL, cand);
            if (mm) {
                float tot = INF_F;
                if (cand) {
                    float dxy = sqrtf(fmaxf(2.0f * (sd + qh), 0.0f));
                    float4 nc = __ldg(sn + pos);
                    float nd = fmaf(-uz, nc.z,
                                    fmaf(-uy, nc.y, fmaf(-ux, nc.x, nc.w)));
                    float dn = sqrtf(fmaxf(2.0f * (nd + uh), 0.0f));
                    tot = dxy + 1.0f / (1.0f + __expf(-dn));
                }
                unsigned m2 = __ballot_sync(FULL, tot < kth);
                if (m2) {
                    while (m2) {
                        int sp = __ffs(m2) - 1;
                        m2 &= m2 - 1;
                        float cd = __shfl_sync(FULL, tot, sp);
                        int ci = __shfl_sync(FULL, pos, sp);
                        warp_insert(cd, ci, d_top, i_top, lane);
                    }
                    kth = __shfl_sync(FULL, d_top, 7);
                    kth05 = kth - 0.5f;
                    pr = fmaf(0.5f * kth05, kth05, -qh);
                }
            }
        }
    }

    // ---- Output: 8 lanes in parallel ----
    float r = (lane < 8) ? 1.0f / (d_top + 1e-8f) : 0.0f;
    float sum = r;
#pragma unroll
    for (int off = 1; off < 32; off <<= 1)
        sum += __shfl_xor_sync(FULL, sum, off);
    if (lane < 8) {
        float w = r / sum;
        int oi = __ldg(g_sid + base + b * S + i_top);
        float* o = g_wiv + wbase + ((size_t)b * N + n) * 16;
        o[lane] = w;
        o[8 + lane] = __int_as_float(oi);
    }
}

// ---------------------------------------------------------------------------
// Shared interp body: one (query, 64-lane slice) unit.
// ---------------------------------------------------------------------------
__device__ __forceinline__ void interp_one(
    const float* __restrict__ p1, const float* __restrict__ p2,
    float* __restrict__ out, int N, int S, int wbase, int b, int n, int l)
{
    const float4* wv = (const float4*)(g_wiv + wbase + ((size_t)b * N + n) * 16);
    float4 w0 = __ldg(wv + 0), w1 = __ldg(wv + 1);
    float4 f0 = __ldg(wv + 2), f1 = __ldg(wv + 3);

    const float4* __restrict__ P = (const float4*)p2 + (size_t)b * S * (C / 4);
    float4 acc;
    {
        float4 r0 = __ldg(P + (size_t)__float_as_int(f0.x) * (C / 4) + l);
        acc.x = w0.x * r0.x; acc.y = w0.x * r0.y;
        acc.z = w0.x * r0.z; acc.w = w0.x * r0.w;
    }
#define GATHER(W, IDX)                                                         \
    {                                                                          \
        float4 r_ = __ldg(P + (size_t)__float_as_int(IDX) * (C / 4) + l);      \
        acc.x = fmaf(W, r_.x, acc.x); acc.y = fmaf(W, r_.y, acc.y);            \
        acc.z = fmaf(W, r_.z, acc.z); acc.w = fmaf(W, r_.w, acc.w);            \
    }
    GATHER(w0.y, f0.y) GATHER(w0.z, f0.z) GATHER(w0.w, f0.w)
    GATHER(w1.x, f1.x) GATHER(w1.y, f1.y) GATHER(w1.z, f1.z) GATHER(w1.w, f1.w)
#undef GATHER

    const size_t qo = ((size_t)b * N + n) * (C / 4) + l;
    float4 pv = __ldg((const float4*)p1 + qo);
    float4 o;
    o.x = (fmaxf(pv.x, acc.x) + (pv.x + acc.x) * 0.5f) * 0.5f;
    o.y = (fmaxf(pv.y, acc.y) + (pv.y + acc.y) * 0.5f) * 0.5f;
    o.z = (fmaxf(pv.z, acc.z) + (pv.z + acc.z) * 0.5f) * 0.5f;
    o.w = (fmaxf(pv.w, acc.w) + (pv.w + acc.w) * 0.5f) * 0.5f;
    ((float4*)out)[qo] = o;
}

// ---------------------------------------------------------------------------
// Fused topk: all three stages in one launch. Stage0 blocks also run their
// own interp (p1=feat2, p2=feat3 -> x1) after a block sync.
// blocks: [0,4096) stage2, [4096,5120) stage1, [5120,5376) stage0.
// ---------------------------------------------------------------------------
__global__ void __launch_bounds__(256, 8) topk_fused(
    const float* __restrict__ x0, const float* __restrict__ n0,
    const float* __restrict__ x1, const float* __restrict__ n1,
    const float* __restrict__ x2, const float* __restrict__ n2,
    const float* __restrict__ feat2, const float* __restrict__ feat3,
    float* __restrict__ x1out)
{
    const int bid = blockIdx.x;
    const int warp = threadIdx.x >> 5;
    const int lane = threadIdx.x & 31;
    if (bid < 4096) {
        int lb = bid, b = lb >> 11, n = (lb & 2047) * 8 + warp;
        topk_query<4096, 256>(x0, n0, 16384, 0, 0, WOFF2, b, n, lane);
    } else if (bid < 5120) {
        int lb = bid - 4096, b = lb >> 9, n = (lb & 511) * 8 + warp;
        topk_query<1024, 64>(x1, n1, 4096, 8192, 512, WOFF1, b, n, lane);
    } else {
        int lb = bid - 5120, b = lb >> 7, n = (lb & 127) * 8 + warp;
        topk_query<256, 16>(x2, n2, 1024, 10240, 640, WOFF0, b, n, lane);
        __syncthreads();   // g_wiv writes of all 8 warps visible
        int n_base = (lb & 127) * 8;
#pragma unroll
        for (int rep = 0; rep < 2; rep++) {
            int slot = threadIdx.x + rep * 256;
            interp_one(feat2, feat3, x1out, 1024, 256, WOFF0,
                       b, n_base + (slot >> 6), slot & 63);
        }
    }
}

// ---------------------------------------------------------------------------
// Interpolate: 64 lanes (float4 channels) per query, 4 queries per block.
// ---------------------------------------------------------------------------
__global__ void __launch_bounds__(256) interp_kernel(
    const float* __restrict__ p1, const float* __restrict__ p2,
    float* __restrict__ out, int N, int S, int wbase)
{
    const int b = blockIdx.y;
    const int g = threadIdx.x >> 6;
    const int l = threadIdx.x & 63;
    const int n = blockIdx.x * 4 + g;
    interp_one(p1, p2, out, N, S, wbase, b, n, l);
}

// ---------------------------------------------------------------------------
extern "C" void kernel_launch(void* const* d_in, const int* in_sizes, int n_in,
                              void* d_out, int out_size)
{
    const int B = 2;
    const int Ns[4] = {16384, 4096, 1024, 256};
    const float* xyz[4] = {0, 0, 0, 0};
    const float* nrm[4] = {0, 0, 0, 0};
    const float* feat[4] = {0, 0, 0, 0};

    for (int i = 0; i < n_in; i++) {
        long long cnt = in_sizes[i];
        for (int r = 0; r < 4; r++) {
            long long small = (long long)B * Ns[r] * 3;
            long long big = (long long)B * Ns[r] * C;
            if (cnt == small) {
                if (!xyz[r]) xyz[r] = (const float*)d_in[i];
                else if (!nrm[r]) nrm[r] = (const float*)d_in[i];
                break;
            } else if (cnt == big) {
                if (!feat[r]) feat[r] = (const float*)d_in[i];
                break;
            }
        }
    }

    float* out = (float*)d_out;
    float *x1, *x2;
    cudaGetSymbolAddress((void**)&x1, g_x1);
    cudaGetSymbolAddress((void**)&x2, g_x2);

    // ---- Preprocess (1 launch: fused pack+sort+reorder+spheres) ----
    csort_kernel<<<6, 1024>>>(xyz[1], nrm[1], xyz[2], nrm[2], xyz[3], nrm[3]);

    // ---- All top-k stages + stage0 interp in one launch ----
    topk_fused<<<5376, 256>>>(xyz[0], nrm[0], xyz[1], nrm[1], xyz[2], nrm[2],
                              feat[2], feat[3], x1);

    // ---- Remaining feature propagation chain ----
    interp_kernel<<<dim3(4096 / 4, B), 256>>>(feat[1], x1, x2, 4096, 1024, WOFF1);
    interp_kernel<<<dim3(16384 / 4, B), 256>>>(feat[0], x2, out, 16384, 4096, WOFF2);
}